// round 15
// baseline (speedup 1.0000x reference)
#include <cuda.h>
#include <cuda_runtime.h>

#define BB    2
#define NN    40000
#define C_IN  64
#define MM    40000
#define KNB   16
#define HH    8
#define C_MID 16

#define WARPS_PER_BLOCK 8
#define POINTS_TOTAL    (BB * MM)   // 80000

typedef unsigned long long ull;

__device__ __forceinline__ ull pack2(float lo, float hi) {
    ull r; asm("mov.b64 %0,{%1,%2};" : "=l"(r) : "f"(lo), "f"(hi)); return r;
}
__device__ __forceinline__ void unpack2(float& lo, float& hi, ull v) {
    asm("mov.b64 {%0,%1},%2;" : "=f"(lo), "=f"(hi) : "l"(v));
}
__device__ __forceinline__ void fma2(ull& d, ull a, ull b) {
    asm("fma.rn.f32x2 %0,%1,%2,%3;" : "=l"(d) : "l"(a), "l"(b), "l"(d));
}
__device__ __forceinline__ uint32_t smem_u32(const void* p) {
    uint32_t a;
    asm("{ .reg .u64 t; cvta.to.shared.u64 t, %1; cvt.u32.u64 %0, t; }" : "=r"(a) : "l"(p));
    return a;
}

// ============================ TMA kernel + cp.async f-prefetch (R13 + split waits) ======
// Per-warp:
//   region[1024] floats (4KB): phase1 = gathered f rows [16][256B] (cp.async, MLP=16),
//                              phase2 = SW128-swizzled output tile (TMA store)
//   wg[384] floats (1.5KB):    w[16][16] @0, g[16][8] @256 (cp.async staged)
// Commit groups: {w,g,f0-3}, {f4-7}, {f8-15}; waits at k=0/4/8.
__global__ __launch_bounds__(256, 4)
void pcf_tma(const __grid_constant__ CUtensorMap tmap,
             const float* __restrict__ feats,  // [B,N,64]
             const int*   __restrict__ inds,   // [B,M,16] int32
             const float* __restrict__ guid,   // [B,M,16,8]
             const float* __restrict__ wnet)   // [B,M,16,16]
{
    __shared__ __align__(1024) float region[WARPS_PER_BLOCK][1024];  // 32KB
    __shared__ __align__(16)   float wg[WARPS_PER_BLOCK][384];       // 12KB

    const int warp = threadIdx.x >> 5;
    const int lane = threadIdx.x & 31;
    const long long p = (long long)blockIdx.x * WARPS_PER_BLOCK + warp;

    const uint32_t fbuf  = smem_u32(&region[warp][0]);  // 4KB f rows / epi tile
    const uint32_t wbase = smem_u32(&wg[warp][0]);      // w tile
    const uint32_t gbase = wbase + 1024u;               // g tile
    const float*   g_sh  = &wg[warp][256];
    const float*   f_sh  = &region[warp][0];

    // idx for this point (lanes 0..15); LDG first — cp.async f depends on it
    int myidx = 0;
    if (lane < KNB) myidx = inds[p * KNB + lane];

    // stage w + g via cp.async (independent of idx)
    {
        const float4* w4 = (const float4*)(wnet + p * (KNB * C_MID));
        const float4* g4 = (const float4*)(guid + p * (KNB * HH));
        const uint32_t ws = wbase + 16u * lane;
        asm volatile("cp.async.cg.shared.global [%0], [%1], 16;"
                     :: "r"(ws),        "l"(w4 + lane)      : "memory");
        asm volatile("cp.async.cg.shared.global [%0], [%1], 16;"
                     :: "r"(ws + 512u), "l"(w4 + lane + 32) : "memory");
        asm volatile("cp.async.cg.shared.global [%0], [%1], 16;"
                     :: "r"(gbase + 16u * lane), "l"(g4 + lane) : "memory");
    }

    // gather 16 f rows via cp.async: instr i covers rows 2i (lanes 0-15)
    // and 2i+1 (lanes 16-31), 16B per lane. MLP=16 with zero regs held.
    const int badd = (p >= MM) ? NN : 0;   // batch offset in rows
    const char* fby = (const char*)feats;
    const int half = lane >> 4;
    const uint32_t fdst = fbuf + 16u * lane;
#pragma unroll
    for (int i = 0; i < 2; i++) {          // rows 0..3
        const int r0 = __shfl_sync(0xffffffffu, myidx, 2 * i);
        const int r1 = __shfl_sync(0xffffffffu, myidx, 2 * i + 1);
        const long long row = (long long)((half ? r1 : r0) + badd);
        asm volatile("cp.async.cg.shared.global [%0], [%1], 16;"
                     :: "r"(fdst + 512u * i),
                        "l"(fby + row * 256 + (lane & 15) * 16) : "memory");
    }
    asm volatile("cp.async.commit_group;" ::: "memory");   // G: w,g,f0-3
#pragma unroll
    for (int i = 2; i < 4; i++) {          // rows 4..7
        const int r0 = __shfl_sync(0xffffffffu, myidx, 2 * i);
        const int r1 = __shfl_sync(0xffffffffu, myidx, 2 * i + 1);
        const long long row = (long long)((half ? r1 : r0) + badd);
        asm volatile("cp.async.cg.shared.global [%0], [%1], 16;"
                     :: "r"(fdst + 512u * i),
                        "l"(fby + row * 256 + (lane & 15) * 16) : "memory");
    }
    asm volatile("cp.async.commit_group;" ::: "memory");   // G: f4-7
#pragma unroll
    for (int i = 4; i < 8; i++) {          // rows 8..15
        const int r0 = __shfl_sync(0xffffffffu, myidx, 2 * i);
        const int r1 = __shfl_sync(0xffffffffu, myidx, 2 * i + 1);
        const long long row = (long long)((half ? r1 : r0) + badd);
        asm volatile("cp.async.cg.shared.global [%0], [%1], 16;"
                     :: "r"(fdst + 512u * i),
                        "l"(fby + row * 256 + (lane & 15) * 16) : "memory");
    }
    asm volatile("cp.async.commit_group;" ::: "memory");   // G: f8-15

    // acc c0[j] = out(c=2l, d=2j,2j+1); c1[j] = out(c=2l+1, ...)
    ull c0[8], c1[8];
#pragma unroll
    for (int j = 0; j < 8; j++) { c0[j] = 0ull; c1[j] = 0ull; }

    // wait for w,g + first 4 rows; rest still in flight
    asm volatile("cp.async.wait_group 2;" ::: "memory");
    __syncwarp();

#pragma unroll
    for (int k = 0; k < KNB; k++) {
        if (k == 4) {
            asm volatile("cp.async.wait_group 1;" ::: "memory");
            __syncwarp();
        }
        if (k == 8) {
            asm volatile("cp.async.wait_group 0;" ::: "memory");
            __syncwarp();
        }
        const float2 f = *(const float2*)(f_sh + k * 64 + lane * 2);  // LDS.64
        const float  g = g_sh[k * HH + (lane >> 2)];
        const float a0 = f.x * g, a1 = f.y * g;
        const ull a00 = pack2(a0, a0);
        const ull a11 = pack2(a1, a1);

        ull w01, w23, w45, w67, w89, wab, wcd, wef;
        const uint32_t wa = wbase + k * (C_MID * 4);
        asm("ld.shared.v2.b64 {%0,%1}, [%2];"    : "=l"(w01), "=l"(w23) : "r"(wa));
        asm("ld.shared.v2.b64 {%0,%1}, [%2+16];" : "=l"(w45), "=l"(w67) : "r"(wa));
        asm("ld.shared.v2.b64 {%0,%1}, [%2+32];" : "=l"(w89), "=l"(wab) : "r"(wa));
        asm("ld.shared.v2.b64 {%0,%1}, [%2+48];" : "=l"(wcd), "=l"(wef) : "r"(wa));

        fma2(c0[0], a00, w01); fma2(c0[1], a00, w23);
        fma2(c0[2], a00, w45); fma2(c0[3], a00, w67);
        fma2(c0[4], a00, w89); fma2(c0[5], a00, wab);
        fma2(c0[6], a00, wcd); fma2(c0[7], a00, wef);
        fma2(c1[0], a11, w01); fma2(c1[1], a11, w23);
        fma2(c1[2], a11, w45); fma2(c1[3], a11, w67);
        fma2(c1[4], a11, w89); fma2(c1[5], a11, wab);
        fma2(c1[6], a11, wcd); fma2(c1[7], a11, wef);
    }

    // ---- epilogue: f consumed; reuse region as SW128 tile, one TMA store ----
    __syncwarp();   // cross-lane: all lanes done reading f before overwrite
    const uint32_t obase = fbuf + 128u * lane;
    const uint32_t lsw = (lane & 7);
#pragma unroll
    for (int j = 0; j < 8; j++) {
        const ull u0 = (j < 4) ? c0[2 * j]     : c1[2 * (j - 4)];
        const ull u1 = (j < 4) ? c0[2 * j + 1] : c1[2 * (j - 4) + 1];
        const uint32_t addr = obase + 16u * ((uint32_t)j ^ lsw);
        asm volatile("st.shared.v2.b64 [%0], {%1,%2};" :: "r"(addr), "l"(u0), "l"(u1));
    }
    __syncwarp();

    if (lane == 0) {
        const int row = (int)(p * 32);
        asm volatile("fence.proxy.async.shared::cta;" ::: "memory");
        asm volatile(
            "cp.async.bulk.tensor.2d.global.shared::cta.tile.bulk_group "
            "[%0, {%1, %2}], [%3];"
            :: "l"(&tmap), "r"(0), "r"(row), "r"(fbuf)
            : "memory");
        asm volatile("cp.async.bulk.commit_group;" ::: "memory");
        asm volatile("cp.async.bulk.wait_group.read 0;" ::: "memory");
    }
}

// ============================ fallback (R3, 102us) ============================
#define REGION_F 1152
__device__ __forceinline__ ull mul2_(ull a, ull b) {
    ull r; asm("mul.rn.f32x2 %0,%1,%2;" : "=l"(r) : "l"(a), "l"(b)); return r;
}

__global__ __launch_bounds__(256, 4)
void pcf_fallback(const float* __restrict__ feats, const int* __restrict__ inds,
                  const float* __restrict__ guid, const float* __restrict__ wnet,
                  float* __restrict__ out)
{
    __shared__ float region[WARPS_PER_BLOCK][REGION_F];
    const int warp = threadIdx.x >> 5;
    const int lane = threadIdx.x & 31;
    const long long p = (long long)blockIdx.x * WARPS_PER_BLOCK + warp;

    float* w_sh = &region[warp][0];
    float* g_sh = &region[warp][256];

    int myidx = 0;
    if (lane < KNB) myidx = inds[p * KNB + lane];
    {
        const float4* w4 = (const float4*)(wnet + p * (KNB * C_MID));
        float4* ws4 = (float4*)w_sh;
        ws4[lane]      = w4[lane];
        ws4[lane + 32] = w4[lane + 32];
        const float4* g4 = (const float4*)(guid + p * (KNB * HH));
        ((float4*)g_sh)[lane] = g4[lane];
    }
    __syncwarp();

    const long long b = p / MM;
    const float2* fbase = (const float2*)feats + b * (long long)NN * (C_IN / 2);

    ull acc[C_MID];
#pragma unroll
    for (int d = 0; d < C_MID; d++) acc[d] = 0ull;

#pragma unroll
    for (int k = 0; k < KNB; k++) {
        const int nidx = __shfl_sync(0xffffffffu, myidx, k);
        const float2 f = fbase[(long long)nidx * (C_IN / 2) + lane];
        const float  g = g_sh[k * HH + (lane >> 2)];
        const ull a2 = mul2_(pack2(f.x, f.y), pack2(g, g));
        const float4 w0 = ((const float4*)(w_sh + k * C_MID))[0];
        const float4 w1 = ((const float4*)(w_sh + k * C_MID))[1];
        const float4 w2 = ((const float4*)(w_sh + k * C_MID))[2];
        const float4 w3 = ((const float4*)(w_sh + k * C_MID))[3];
        fma2(acc[0],  a2, pack2(w0.x, w0.x)); fma2(acc[1],  a2, pack2(w0.y, w0.y));
        fma2(acc[2],  a2, pack2(w0.z, w0.z)); fma2(acc[3],  a2, pack2(w0.w, w0.w));
        fma2(acc[4],  a2, pack2(w1.x, w1.x)); fma2(acc[5],  a2, pack2(w1.y, w1.y));
        fma2(acc[6],  a2, pack2(w1.z, w1.z)); fma2(acc[7],  a2, pack2(w1.w, w1.w));
        fma2(acc[8],  a2, pack2(w2.x, w2.x)); fma2(acc[9],  a2, pack2(w2.y, w2.y));
        fma2(acc[10], a2, pack2(w2.z, w2.z)); fma2(acc[11], a2, pack2(w2.w, w2.w));
        fma2(acc[12], a2, pack2(w3.x, w3.x)); fma2(acc[13], a2, pack2(w3.y, w3.y));
        fma2(acc[14], a2, pack2(w3.z, w3.z)); fma2(acc[15], a2, pack2(w3.w, w3.w));
    }

    __syncwarp();
    float4* b4 = (float4*)&region[warp][0];
#pragma unroll
    for (int j = 0; j < 4; j++) {
        float l0, h0, l1, h1, l2, h2, l3, h3;
        unpack2(l0, h0, acc[4*j + 0]); unpack2(l1, h1, acc[4*j + 1]);
        unpack2(l2, h2, acc[4*j + 2]); unpack2(l3, h3, acc[4*j + 3]);
        b4[9 * lane + j]     = make_float4(l0, l1, l2, l3);
        b4[9 * lane + 4 + j] = make_float4(h0, h1, h2, h3);
    }
    __syncwarp();

    float4* og = (float4*)(out + p * (C_IN * C_MID));
#pragma unroll
    for (int i = 0; i < 8; i++) {
        const int L4 = 32 * i + lane;
        og[L4] = b4[9 * (L4 >> 3) + (L4 & 7)];
    }
}

// ============================ host launcher ============================
typedef CUresult (*EncodeFn)(CUtensorMap*, CUtensorMapDataType, cuuint32_t, void*,
                             const cuuint64_t*, const cuuint64_t*,
                             const cuuint32_t*, const cuuint32_t*,
                             CUtensorMapInterleave, CUtensorMapSwizzle,
                             CUtensorMapL2promotion, CUtensorMapFloatOOBfill);

extern "C" void kernel_launch(void* const* d_in, const int* in_sizes, int n_in,
                              void* d_out, int out_size)
{
    const float* feats = (const float*)d_in[0];
    const int*   inds  = (const int*)d_in[1];
    const float* guid  = (const float*)d_in[2];
    const float* wnet  = (const float*)d_in[3];

    void* fn = nullptr;
    cudaDriverEntryPointQueryResult qres;
    bool ok = (cudaGetDriverEntryPoint("cuTensorMapEncodeTiled", &fn,
                                       cudaEnableDefault, &qres) == cudaSuccess) && fn;
    CUtensorMap tmap;
    if (ok) {
        cuuint64_t dims[2]    = { 32ull, (cuuint64_t)POINTS_TOTAL * 32ull };
        cuuint64_t strides[1] = { 128ull };
        cuuint32_t box[2]     = { 32u, 32u };
        cuuint32_t estr[2]    = { 1u, 1u };
        CUresult r = ((EncodeFn)fn)(&tmap, CU_TENSOR_MAP_DATA_TYPE_FLOAT32, 2, d_out,
                                    dims, strides, box, estr,
                                    CU_TENSOR_MAP_INTERLEAVE_NONE,
                                    CU_TENSOR_MAP_SWIZZLE_128B,
                                    CU_TENSOR_MAP_L2_PROMOTION_L2_128B,
                                    CU_TENSOR_MAP_FLOAT_OOB_FILL_NONE);
        ok = (r == CUDA_SUCCESS);
    }

    const int blocks = POINTS_TOTAL / WARPS_PER_BLOCK; // 10000
    if (ok) {
        pcf_tma<<<blocks, 256>>>(tmap, feats, inds, guid, wnet);
    } else {
        pcf_fallback<<<blocks, 256>>>(feats, inds, guid, wnet, (float*)d_out);
    }
}

// round 16
// speedup vs baseline: 1.0238x; 1.0238x over previous
#include <cuda.h>
#include <cuda_runtime.h>

#define BB    2
#define NN    40000
#define C_IN  64
#define MM    40000
#define KNB   16
#define HH    8
#define C_MID 16

#define WARPS_PER_BLOCK 8
#define POINTS_TOTAL    (BB * MM)   // 80000

typedef unsigned long long ull;

__device__ __forceinline__ ull pack2(float lo, float hi) {
    ull r; asm("mov.b64 %0,{%1,%2};" : "=l"(r) : "f"(lo), "f"(hi)); return r;
}
__device__ __forceinline__ void unpack2(float& lo, float& hi, ull v) {
    asm("mov.b64 {%0,%1},%2;" : "=f"(lo), "=f"(hi) : "l"(v));
}
__device__ __forceinline__ void fma2(ull& d, ull a, ull b) {
    asm("fma.rn.f32x2 %0,%1,%2,%3;" : "=l"(d) : "l"(a), "l"(b), "l"(d));
}
__device__ __forceinline__ uint32_t smem_u32(const void* p) {
    uint32_t a;
    asm("{ .reg .u64 t; cvta.to.shared.u64 t, %1; cvt.u32.u64 %0, t; }" : "=r"(a) : "l"(p));
    return a;
}

// ============================ TMA kernel + cp.async f-prefetch (R13 champion) ==========
// Per-warp:
//   region[1024] floats (4KB): phase1 = gathered f rows [16][256B] (cp.async, MLP=16),
//                              phase2 = SW128-swizzled output tile (TMA store)
//   wg[384] floats (1.5KB):    w[16][16] @0, g[16][8] @256 (cp.async staged)
// Mainloop is pure LDS + FMA2 (no gather LDG, no SHFL).
__global__ __launch_bounds__(256, 4)
void pcf_tma(const __grid_constant__ CUtensorMap tmap,
             const float* __restrict__ feats,  // [B,N,64]
             const int*   __restrict__ inds,   // [B,M,16] int32
             const float* __restrict__ guid,   // [B,M,16,8]
             const float* __restrict__ wnet)   // [B,M,16,16]
{
    __shared__ __align__(1024) float region[WARPS_PER_BLOCK][1024];  // 32KB
    __shared__ __align__(16)   float wg[WARPS_PER_BLOCK][384];       // 12KB

    const int warp = threadIdx.x >> 5;
    const int lane = threadIdx.x & 31;
    const long long p = (long long)blockIdx.x * WARPS_PER_BLOCK + warp;

    const uint32_t fbuf  = smem_u32(&region[warp][0]);  // 4KB f rows / epi tile
    const uint32_t wbase = smem_u32(&wg[warp][0]);      // w tile
    const uint32_t gbase = wbase + 1024u;               // g tile
    const float*   g_sh  = &wg[warp][256];
    const float*   f_sh  = &region[warp][0];

    // idx for this point (lanes 0..15); LDG first — cp.async f depends on it
    int myidx = 0;
    if (lane < KNB) myidx = inds[p * KNB + lane];

    // stage w + g via cp.async (independent of idx)
    {
        const float4* w4 = (const float4*)(wnet + p * (KNB * C_MID));
        const float4* g4 = (const float4*)(guid + p * (KNB * HH));
        const uint32_t ws = wbase + 16u * lane;
        asm volatile("cp.async.cg.shared.global [%0], [%1], 16;"
                     :: "r"(ws),        "l"(w4 + lane)      : "memory");
        asm volatile("cp.async.cg.shared.global [%0], [%1], 16;"
                     :: "r"(ws + 512u), "l"(w4 + lane + 32) : "memory");
        asm volatile("cp.async.cg.shared.global [%0], [%1], 16;"
                     :: "r"(gbase + 16u * lane), "l"(g4 + lane) : "memory");
    }

    // gather all 16 f rows via cp.async: instr i covers rows 2i (lanes 0-15)
    // and 2i+1 (lanes 16-31), 16B chunk per lane. MLP=16 with zero regs held.
    const int badd = (p >= MM) ? NN : 0;   // batch offset in rows
    const char* fby = (const char*)feats;
    const int half = lane >> 4;            // 0: even row of pair, 1: odd
    const uint32_t fdst = fbuf + 16u * lane;
#pragma unroll
    for (int i = 0; i < 4; i++) {          // rows 0..7
        const int r0 = __shfl_sync(0xffffffffu, myidx, 2 * i);
        const int r1 = __shfl_sync(0xffffffffu, myidx, 2 * i + 1);
        const long long row = (long long)((half ? r1 : r0) + badd);
        const char* src = fby + row * 256 + (lane & 15) * 16;
        asm volatile("cp.async.cg.shared.global [%0], [%1], 16;"
                     :: "r"(fdst + 512u * i), "l"(src) : "memory");
    }
    asm volatile("cp.async.commit_group;" ::: "memory");   // group1: w,g,f rows 0-7
#pragma unroll
    for (int i = 4; i < 8; i++) {          // rows 8..15
        const int r0 = __shfl_sync(0xffffffffu, myidx, 2 * i);
        const int r1 = __shfl_sync(0xffffffffu, myidx, 2 * i + 1);
        const long long row = (long long)((half ? r1 : r0) + badd);
        const char* src = fby + row * 256 + (lane & 15) * 16;
        asm volatile("cp.async.cg.shared.global [%0], [%1], 16;"
                     :: "r"(fdst + 512u * i), "l"(src) : "memory");
    }
    asm volatile("cp.async.commit_group;" ::: "memory");   // group0: f rows 8-15

    // acc c0[j] = out(c=2l, d=2j,2j+1); c1[j] = out(c=2l+1, ...)
    ull c0[8], c1[8];
#pragma unroll
    for (int j = 0; j < 8; j++) { c0[j] = 0ull; c1[j] = 0ull; }

    // wait for w,g + first 8 rows; second half still in flight
    asm volatile("cp.async.wait_group 1;" ::: "memory");
    __syncwarp();

#pragma unroll
    for (int k = 0; k < KNB; k++) {
        if (k == 8) {   // second half of f rows
            asm volatile("cp.async.wait_group 0;" ::: "memory");
            __syncwarp();
        }
        const float2 f = *(const float2*)(f_sh + k * 64 + lane * 2);  // LDS.64
        const float  g = g_sh[k * HH + (lane >> 2)];
        const float a0 = f.x * g, a1 = f.y * g;
        const ull a00 = pack2(a0, a0);
        const ull a11 = pack2(a1, a1);

        ull w01, w23, w45, w67, w89, wab, wcd, wef;
        const uint32_t wa = wbase + k * (C_MID * 4);
        asm("ld.shared.v2.b64 {%0,%1}, [%2];"    : "=l"(w01), "=l"(w23) : "r"(wa));
        asm("ld.shared.v2.b64 {%0,%1}, [%2+16];" : "=l"(w45), "=l"(w67) : "r"(wa));
        asm("ld.shared.v2.b64 {%0,%1}, [%2+32];" : "=l"(w89), "=l"(wab) : "r"(wa));
        asm("ld.shared.v2.b64 {%0,%1}, [%2+48];" : "=l"(wcd), "=l"(wef) : "r"(wa));

        fma2(c0[0], a00, w01); fma2(c0[1], a00, w23);
        fma2(c0[2], a00, w45); fma2(c0[3], a00, w67);
        fma2(c0[4], a00, w89); fma2(c0[5], a00, wab);
        fma2(c0[6], a00, wcd); fma2(c0[7], a00, wef);
        fma2(c1[0], a11, w01); fma2(c1[1], a11, w23);
        fma2(c1[2], a11, w45); fma2(c1[3], a11, w67);
        fma2(c1[4], a11, w89); fma2(c1[5], a11, wab);
        fma2(c1[6], a11, wcd); fma2(c1[7], a11, wef);
    }

    // ---- epilogue: f consumed; reuse region as SW128 tile, one TMA store ----
    __syncwarp();   // cross-lane: all lanes done reading f before overwrite
    const uint32_t obase = fbuf + 128u * lane;
    const uint32_t lsw = (lane & 7);
#pragma unroll
    for (int j = 0; j < 8; j++) {
        const ull u0 = (j < 4) ? c0[2 * j]     : c1[2 * (j - 4)];
        const ull u1 = (j < 4) ? c0[2 * j + 1] : c1[2 * (j - 4) + 1];
        const uint32_t addr = obase + 16u * ((uint32_t)j ^ lsw);
        asm volatile("st.shared.v2.b64 [%0], {%1,%2};" :: "r"(addr), "l"(u0), "l"(u1));
    }
    __syncwarp();

    if (lane == 0) {
        const int row = (int)(p * 32);
        asm volatile("fence.proxy.async.shared::cta;" ::: "memory");
        asm volatile(
            "cp.async.bulk.tensor.2d.global.shared::cta.tile.bulk_group "
            "[%0, {%1, %2}], [%3];"
            :: "l"(&tmap), "r"(0), "r"(row), "r"(fbuf)
            : "memory");
        asm volatile("cp.async.bulk.commit_group;" ::: "memory");
        asm volatile("cp.async.bulk.wait_group.read 0;" ::: "memory");
    }
}

// ============================ fallback (R3, 102us) ============================
#define REGION_F 1152
__device__ __forceinline__ ull mul2_(ull a, ull b) {
    ull r; asm("mul.rn.f32x2 %0,%1,%2;" : "=l"(r) : "l"(a), "l"(b)); return r;
}

__global__ __launch_bounds__(256, 4)
void pcf_fallback(const float* __restrict__ feats, const int* __restrict__ inds,
                  const float* __restrict__ guid, const float* __restrict__ wnet,
                  float* __restrict__ out)
{
    __shared__ float region[WARPS_PER_BLOCK][REGION_F];
    const int warp = threadIdx.x >> 5;
    const int lane = threadIdx.x & 31;
    const long long p = (long long)blockIdx.x * WARPS_PER_BLOCK + warp;

    float* w_sh = &region[warp][0];
    float* g_sh = &region[warp][256];

    int myidx = 0;
    if (lane < KNB) myidx = inds[p * KNB + lane];
    {
        const float4* w4 = (const float4*)(wnet + p * (KNB * C_MID));
        float4* ws4 = (float4*)w_sh;
        ws4[lane]      = w4[lane];
        ws4[lane + 32] = w4[lane + 32];
        const float4* g4 = (const float4*)(guid + p * (KNB * HH));
        ((float4*)g_sh)[lane] = g4[lane];
    }
    __syncwarp();

    const long long b = p / MM;
    const float2* fbase = (const float2*)feats + b * (long long)NN * (C_IN / 2);

    ull acc[C_MID];
#pragma unroll
    for (int d = 0; d < C_MID; d++) acc[d] = 0ull;

#pragma unroll
    for (int k = 0; k < KNB; k++) {
        const int nidx = __shfl_sync(0xffffffffu, myidx, k);
        const float2 f = fbase[(long long)nidx * (C_IN / 2) + lane];
        const float  g = g_sh[k * HH + (lane >> 2)];
        const ull a2 = mul2_(pack2(f.x, f.y), pack2(g, g));
        const float4 w0 = ((const float4*)(w_sh + k * C_MID))[0];
        const float4 w1 = ((const float4*)(w_sh + k * C_MID))[1];
        const float4 w2 = ((const float4*)(w_sh + k * C_MID))[2];
        const float4 w3 = ((const float4*)(w_sh + k * C_MID))[3];
        fma2(acc[0],  a2, pack2(w0.x, w0.x)); fma2(acc[1],  a2, pack2(w0.y, w0.y));
        fma2(acc[2],  a2, pack2(w0.z, w0.z)); fma2(acc[3],  a2, pack2(w0.w, w0.w));
        fma2(acc[4],  a2, pack2(w1.x, w1.x)); fma2(acc[5],  a2, pack2(w1.y, w1.y));
        fma2(acc[6],  a2, pack2(w1.z, w1.z)); fma2(acc[7],  a2, pack2(w1.w, w1.w));
        fma2(acc[8],  a2, pack2(w2.x, w2.x)); fma2(acc[9],  a2, pack2(w2.y, w2.y));
        fma2(acc[10], a2, pack2(w2.z, w2.z)); fma2(acc[11], a2, pack2(w2.w, w2.w));
        fma2(acc[12], a2, pack2(w3.x, w3.x)); fma2(acc[13], a2, pack2(w3.y, w3.y));
        fma2(acc[14], a2, pack2(w3.z, w3.z)); fma2(acc[15], a2, pack2(w3.w, w3.w));
    }

    __syncwarp();
    float4* b4 = (float4*)&region[warp][0];
#pragma unroll
    for (int j = 0; j < 4; j++) {
        float l0, h0, l1, h1, l2, h2, l3, h3;
        unpack2(l0, h0, acc[4*j + 0]); unpack2(l1, h1, acc[4*j + 1]);
        unpack2(l2, h2, acc[4*j + 2]); unpack2(l3, h3, acc[4*j + 3]);
        b4[9 * lane + j]     = make_float4(l0, l1, l2, l3);
        b4[9 * lane + 4 + j] = make_float4(h0, h1, h2, h3);
    }
    __syncwarp();

    float4* og = (float4*)(out + p * (C_IN * C_MID));
#pragma unroll
    for (int i = 0; i < 8; i++) {
        const int L4 = 32 * i + lane;
        og[L4] = b4[9 * (L4 >> 3) + (L4 & 7)];
    }
}

// ============================ host launcher ============================
typedef CUresult (*EncodeFn)(CUtensorMap*, CUtensorMapDataType, cuuint32_t, void*,
                             const cuuint64_t*, const cuuint64_t*,
                             const cuuint32_t*, const cuuint32_t*,
                             CUtensorMapInterleave, CUtensorMapSwizzle,
                             CUtensorMapL2promotion, CUtensorMapFloatOOBfill);

extern "C" void kernel_launch(void* const* d_in, const int* in_sizes, int n_in,
                              void* d_out, int out_size)
{
    const float* feats = (const float*)d_in[0];
    const int*   inds  = (const int*)d_in[1];
    const float* guid  = (const float*)d_in[2];
    const float* wnet  = (const float*)d_in[3];

    void* fn = nullptr;
    cudaDriverEntryPointQueryResult qres;
    bool ok = (cudaGetDriverEntryPoint("cuTensorMapEncodeTiled", &fn,
                                       cudaEnableDefault, &qres) == cudaSuccess) && fn;
    CUtensorMap tmap;
    if (ok) {
        cuuint64_t dims[2]    = { 32ull, (cuuint64_t)POINTS_TOTAL * 32ull };
        cuuint64_t strides[1] = { 128ull };
        cuuint32_t box[2]     = { 32u, 32u };
        cuuint32_t estr[2]    = { 1u, 1u };
        CUresult r = ((EncodeFn)fn)(&tmap, CU_TENSOR_MAP_DATA_TYPE_FLOAT32, 2, d_out,
                                    dims, strides, box, estr,
                                    CU_TENSOR_MAP_INTERLEAVE_NONE,
                                    CU_TENSOR_MAP_SWIZZLE_128B,
                                    CU_TENSOR_MAP_L2_PROMOTION_L2_128B,
                                    CU_TENSOR_MAP_FLOAT_OOB_FILL_NONE);
        ok = (r == CUDA_SUCCESS);
    }

    const int blocks = POINTS_TOTAL / WARPS_PER_BLOCK; // 10000
    if (ok) {
        pcf_tma<<<blocks, 256>>>(tmap, feats, inds, guid, wnet);
    } else {
        pcf_fallback<<<blocks, 256>>>(feats, inds, guid, wnet, (float*)d_out);
    }
}

// round 17
// speedup vs baseline: 1.0404x; 1.0162x over previous
#include <cuda.h>
#include <cuda_runtime.h>

#define BB    2
#define NN    40000
#define C_IN  64
#define MM    40000
#define KNB   16
#define HH    8
#define C_MID 16

#define WARPS_PER_BLOCK 8
#define POINTS_TOTAL    (BB * MM)   // 80000

typedef unsigned long long ull;

__device__ __forceinline__ ull pack2(float lo, float hi) {
    ull r; asm("mov.b64 %0,{%1,%2};" : "=l"(r) : "f"(lo), "f"(hi)); return r;
}
__device__ __forceinline__ void unpack2(float& lo, float& hi, ull v) {
    asm("mov.b64 {%0,%1},%2;" : "=f"(lo), "=f"(hi) : "l"(v));
}
__device__ __forceinline__ void fma2(ull& d, ull a, ull b) {
    asm("fma.rn.f32x2 %0,%1,%2,%3;" : "=l"(d) : "l"(a), "l"(b), "l"(d));
}
__device__ __forceinline__ uint32_t smem_u32(const void* p) {
    uint32_t a;
    asm("{ .reg .u64 t; cvta.to.shared.u64 t, %1; cvt.u32.u64 %0, t; }" : "=r"(a) : "l"(p));
    return a;
}

// ============================ TMA kernel + cp.async f-prefetch (champion) ==========
// Per-warp:
//   region[1024] floats (4KB): phase1 = gathered f rows [16][256B] (cp.async, MLP=16),
//                              phase2 = SW128-swizzled output tile (TMA store)
//   wg[384] floats (1.5KB):    w[16][16] @0, g[16][8] @256 (cp.async staged)
// Mainloop is pure LDS + FMA2 (no gather LDG, no SHFL).
__global__ __launch_bounds__(256, 4)
void pcf_tma(const __grid_constant__ CUtensorMap tmap,
             const float* __restrict__ feats,  // [B,N,64]
             const int*   __restrict__ inds,   // [B,M,16] int32
             const float* __restrict__ guid,   // [B,M,16,8]
             const float* __restrict__ wnet)   // [B,M,16,16]
{
    __shared__ __align__(1024) float region[WARPS_PER_BLOCK][1024];  // 32KB
    __shared__ __align__(16)   float wg[WARPS_PER_BLOCK][384];       // 12KB

    const int warp = threadIdx.x >> 5;
    const int lane = threadIdx.x & 31;
    const long long p = (long long)blockIdx.x * WARPS_PER_BLOCK + warp;

    const uint32_t fbuf  = smem_u32(&region[warp][0]);  // 4KB f rows / epi tile
    const uint32_t wbase = smem_u32(&wg[warp][0]);      // w tile
    const uint32_t gbase = wbase + 1024u;               // g tile
    const float*   g_sh  = &wg[warp][256];
    const float*   f_sh  = &region[warp][0];

    // idx for this point (lanes 0..15); LDG first — cp.async f depends on it
    int myidx = 0;
    if (lane < KNB) myidx = inds[p * KNB + lane];

    // stage w + g via cp.async (independent of idx)
    {
        const float4* w4 = (const float4*)(wnet + p * (KNB * C_MID));
        const float4* g4 = (const float4*)(guid + p * (KNB * HH));
        const uint32_t ws = wbase + 16u * lane;
        asm volatile("cp.async.cg.shared.global [%0], [%1], 16;"
                     :: "r"(ws),        "l"(w4 + lane)      : "memory");
        asm volatile("cp.async.cg.shared.global [%0], [%1], 16;"
                     :: "r"(ws + 512u), "l"(w4 + lane + 32) : "memory");
        asm volatile("cp.async.cg.shared.global [%0], [%1], 16;"
                     :: "r"(gbase + 16u * lane), "l"(g4 + lane) : "memory");
    }

    // gather all 16 f rows via cp.async: instr i covers rows 2i (lanes 0-15)
    // and 2i+1 (lanes 16-31), 16B chunk per lane. MLP=16 with zero regs held.
    // Batch offset folded into base pointer; row byte-offset is 32-bit
    // (row*256 <= 20.5MB < 2^31) -> single IMAD.WIDE per address.
    const char* fb2 = (const char*)feats
                    + (p >= MM ? (long long)NN * 256 : 0ll)
                    + (lane & 15) * 16;
    const int half = lane >> 4;            // 0: even row of pair, 1: odd
    const uint32_t fdst = fbuf + 16u * lane;
#pragma unroll
    for (int i = 0; i < 4; i++) {          // rows 0..7
        const int r0 = __shfl_sync(0xffffffffu, myidx, 2 * i);
        const int r1 = __shfl_sync(0xffffffffu, myidx, 2 * i + 1);
        const uint32_t off = (uint32_t)(half ? r1 : r0) << 8;
        asm volatile("cp.async.cg.shared.global [%0], [%1], 16;"
                     :: "r"(fdst + 512u * i), "l"(fb2 + off) : "memory");
    }
    asm volatile("cp.async.commit_group;" ::: "memory");   // group1: w,g,f rows 0-7
#pragma unroll
    for (int i = 4; i < 8; i++) {          // rows 8..15
        const int r0 = __shfl_sync(0xffffffffu, myidx, 2 * i);
        const int r1 = __shfl_sync(0xffffffffu, myidx, 2 * i + 1);
        const uint32_t off = (uint32_t)(half ? r1 : r0) << 8;
        asm volatile("cp.async.cg.shared.global [%0], [%1], 16;"
                     :: "r"(fdst + 512u * i), "l"(fb2 + off) : "memory");
    }
    asm volatile("cp.async.commit_group;" ::: "memory");   // group0: f rows 8-15

    // acc c0[j] = out(c=2l, d=2j,2j+1); c1[j] = out(c=2l+1, ...)
    ull c0[8], c1[8];
#pragma unroll
    for (int j = 0; j < 8; j++) { c0[j] = 0ull; c1[j] = 0ull; }

    // wait for w,g + first 8 rows; second half still in flight
    asm volatile("cp.async.wait_group 1;" ::: "memory");
    __syncwarp();

#pragma unroll
    for (int k = 0; k < KNB; k++) {
        if (k == 8) {   // second half of f rows
            asm volatile("cp.async.wait_group 0;" ::: "memory");
            __syncwarp();
        }
        const float2 f = *(const float2*)(f_sh + k * 64 + lane * 2);  // LDS.64
        const float  g = g_sh[k * HH + (lane >> 2)];
        const float a0 = f.x * g, a1 = f.y * g;
        const ull a00 = pack2(a0, a0);
        const ull a11 = pack2(a1, a1);

        ull w01, w23, w45, w67, w89, wab, wcd, wef;
        const uint32_t wa = wbase + k * (C_MID * 4);
        asm("ld.shared.v2.b64 {%0,%1}, [%2];"    : "=l"(w01), "=l"(w23) : "r"(wa));
        asm("ld.shared.v2.b64 {%0,%1}, [%2+16];" : "=l"(w45), "=l"(w67) : "r"(wa));
        asm("ld.shared.v2.b64 {%0,%1}, [%2+32];" : "=l"(w89), "=l"(wab) : "r"(wa));
        asm("ld.shared.v2.b64 {%0,%1}, [%2+48];" : "=l"(wcd), "=l"(wef) : "r"(wa));

        fma2(c0[0], a00, w01); fma2(c0[1], a00, w23);
        fma2(c0[2], a00, w45); fma2(c0[3], a00, w67);
        fma2(c0[4], a00, w89); fma2(c0[5], a00, wab);
        fma2(c0[6], a00, wcd); fma2(c0[7], a00, wef);
        fma2(c1[0], a11, w01); fma2(c1[1], a11, w23);
        fma2(c1[2], a11, w45); fma2(c1[3], a11, w67);
        fma2(c1[4], a11, w89); fma2(c1[5], a11, wab);
        fma2(c1[6], a11, wcd); fma2(c1[7], a11, wef);
    }

    // ---- epilogue: f consumed; reuse region as SW128 tile, one TMA store ----
    __syncwarp();   // cross-lane: all lanes done reading f before overwrite
    const uint32_t obase = fbuf + 128u * lane;
    const uint32_t lsw = (lane & 7);
#pragma unroll
    for (int j = 0; j < 8; j++) {
        const ull u0 = (j < 4) ? c0[2 * j]     : c1[2 * (j - 4)];
        const ull u1 = (j < 4) ? c0[2 * j + 1] : c1[2 * (j - 4) + 1];
        const uint32_t addr = obase + 16u * ((uint32_t)j ^ lsw);
        asm volatile("st.shared.v2.b64 [%0], {%1,%2};" :: "r"(addr), "l"(u0), "l"(u1));
    }
    __syncwarp();

    if (lane == 0) {
        const int row = (int)(p * 32);
        asm volatile("fence.proxy.async.shared::cta;" ::: "memory");
        asm volatile(
            "cp.async.bulk.tensor.2d.global.shared::cta.tile.bulk_group "
            "[%0, {%1, %2}], [%3];"
            :: "l"(&tmap), "r"(0), "r"(row), "r"(fbuf)
            : "memory");
        asm volatile("cp.async.bulk.commit_group;" ::: "memory");
        asm volatile("cp.async.bulk.wait_group.read 0;" ::: "memory");
    }
}

// ============================ fallback (R3, 102us) ============================
#define REGION_F 1152
__device__ __forceinline__ ull mul2_(ull a, ull b) {
    ull r; asm("mul.rn.f32x2 %0,%1,%2;" : "=l"(r) : "l"(a), "l"(b)); return r;
}

__global__ __launch_bounds__(256, 4)
void pcf_fallback(const float* __restrict__ feats, const int* __restrict__ inds,
                  const float* __restrict__ guid, const float* __restrict__ wnet,
                  float* __restrict__ out)
{
    __shared__ float region[WARPS_PER_BLOCK][REGION_F];
    const int warp = threadIdx.x >> 5;
    const int lane = threadIdx.x & 31;
    const long long p = (long long)blockIdx.x * WARPS_PER_BLOCK + warp;

    float* w_sh = &region[warp][0];
    float* g_sh = &region[warp][256];

    int myidx = 0;
    if (lane < KNB) myidx = inds[p * KNB + lane];
    {
        const float4* w4 = (const float4*)(wnet + p * (KNB * C_MID));
        float4* ws4 = (float4*)w_sh;
        ws4[lane]      = w4[lane];
        ws4[lane + 32] = w4[lane + 32];
        const float4* g4 = (const float4*)(guid + p * (KNB * HH));
        ((float4*)g_sh)[lane] = g4[lane];
    }
    __syncwarp();

    const long long b = p / MM;
    const float2* fbase = (const float2*)feats + b * (long long)NN * (C_IN / 2);

    ull acc[C_MID];
#pragma unroll
    for (int d = 0; d < C_MID; d++) acc[d] = 0ull;

#pragma unroll
    for (int k = 0; k < KNB; k++) {
        const int nidx = __shfl_sync(0xffffffffu, myidx, k);
        const float2 f = fbase[(long long)nidx * (C_IN / 2) + lane];
        const float  g = g_sh[k * HH + (lane >> 2)];
        const ull a2 = mul2_(pack2(f.x, f.y), pack2(g, g));
        const float4 w0 = ((const float4*)(w_sh + k * C_MID))[0];
        const float4 w1 = ((const float4*)(w_sh + k * C_MID))[1];
        const float4 w2 = ((const float4*)(w_sh + k * C_MID))[2];
        const float4 w3 = ((const float4*)(w_sh + k * C_MID))[3];
        fma2(acc[0],  a2, pack2(w0.x, w0.x)); fma2(acc[1],  a2, pack2(w0.y, w0.y));
        fma2(acc[2],  a2, pack2(w0.z, w0.z)); fma2(acc[3],  a2, pack2(w0.w, w0.w));
        fma2(acc[4],  a2, pack2(w1.x, w1.x)); fma2(acc[5],  a2, pack2(w1.y, w1.y));
        fma2(acc[6],  a2, pack2(w1.z, w1.z)); fma2(acc[7],  a2, pack2(w1.w, w1.w));
        fma2(acc[8],  a2, pack2(w2.x, w2.x)); fma2(acc[9],  a2, pack2(w2.y, w2.y));
        fma2(acc[10], a2, pack2(w2.z, w2.z)); fma2(acc[11], a2, pack2(w2.w, w2.w));
        fma2(acc[12], a2, pack2(w3.x, w3.x)); fma2(acc[13], a2, pack2(w3.y, w3.y));
        fma2(acc[14], a2, pack2(w3.z, w3.z)); fma2(acc[15], a2, pack2(w3.w, w3.w));
    }

    __syncwarp();
    float4* b4 = (float4*)&region[warp][0];
#pragma unroll
    for (int j = 0; j < 4; j++) {
        float l0, h0, l1, h1, l2, h2, l3, h3;
        unpack2(l0, h0, acc[4*j + 0]); unpack2(l1, h1, acc[4*j + 1]);
        unpack2(l2, h2, acc[4*j + 2]); unpack2(l3, h3, acc[4*j + 3]);
        b4[9 * lane + j]     = make_float4(l0, l1, l2, l3);
        b4[9 * lane + 4 + j] = make_float4(h0, h1, h2, h3);
    }
    __syncwarp();

    float4* og = (float4*)(out + p * (C_IN * C_MID));
#pragma unroll
    for (int i = 0; i < 8; i++) {
        const int L4 = 32 * i + lane;
        og[L4] = b4[9 * (L4 >> 3) + (L4 & 7)];
    }
}

// ============================ host launcher ============================
typedef CUresult (*EncodeFn)(CUtensorMap*, CUtensorMapDataType, cuuint32_t, void*,
                             const cuuint64_t*, const cuuint64_t*,
                             const cuuint32_t*, const cuuint32_t*,
                             CUtensorMapInterleave, CUtensorMapSwizzle,
                             CUtensorMapL2promotion, CUtensorMapFloatOOBfill);

extern "C" void kernel_launch(void* const* d_in, const int* in_sizes, int n_in,
                              void* d_out, int out_size)
{
    const float* feats = (const float*)d_in[0];
    const int*   inds  = (const int*)d_in[1];
    const float* guid  = (const float*)d_in[2];
    const float* wnet  = (const float*)d_in[3];

    void* fn = nullptr;
    cudaDriverEntryPointQueryResult qres;
    bool ok = (cudaGetDriverEntryPoint("cuTensorMapEncodeTiled", &fn,
                                       cudaEnableDefault, &qres) == cudaSuccess) && fn;
    CUtensorMap tmap;
    if (ok) {
        cuuint64_t dims[2]    = { 32ull, (cuuint64_t)POINTS_TOTAL * 32ull };
        cuuint64_t strides[1] = { 128ull };
        cuuint32_t box[2]     = { 32u, 32u };
        cuuint32_t estr[2]    = { 1u, 1u };
        CUresult r = ((EncodeFn)fn)(&tmap, CU_TENSOR_MAP_DATA_TYPE_FLOAT32, 2, d_out,
                                    dims, strides, box, estr,
                                    CU_TENSOR_MAP_INTERLEAVE_NONE,
                                    CU_TENSOR_MAP_SWIZZLE_128B,
                                    CU_TENSOR_MAP_L2_PROMOTION_L2_128B,
                                    CU_TENSOR_MAP_FLOAT_OOB_FILL_NONE);
        ok = (r == CUDA_SUCCESS);
    }

    const int blocks = POINTS_TOTAL / WARPS_PER_BLOCK; // 10000
    if (ok) {
        pcf_tma<<<blocks, 256>>>(tmap, feats, inds, guid, wnet);
    } else {
        pcf_fallback<<<blocks, 256>>>(feats, inds, guid, wnet, (float*)d_out);
    }
}